// round 13
// baseline (speedup 1.0000x reference)
#include <cuda_runtime.h>
#include <math.h>
#include <float.h>

#define BB 32
#define AA 8400
#define GG 40
#define CC 80
#define ROW 85
#define SP 1536      // max candidates per batch; true bound ~1080
#define SPW (SP/32)  // 48 u32 words of transposed in-region bits per (b,g)
#define MM 512       // max matched anchors per batch
#define SL 64        // in-region pairs per (b,g) cap (geometric bound ~48)

// ---------------- scratch (device globals; zero-init at load) ----------------
__device__ unsigned long long d_match[BB * AA];
__device__ unsigned long long d_inin [BB * AA];
__device__ unsigned long long d_cinin[BB * SP];
__device__ unsigned d_ginin[BB * GG * SPW];   // transposed: bit c of word -> cand
__device__ int    d_fgidx[BB * SP];
__device__ int    d_inv  [BB * AA];
__device__ int    d_fgcnt[BB];
__device__ int    d_mcnt [BB];     // reset by last fgloss block
__device__ int    d_midx [BB * MM];
__device__ int    d_done;          // fgloss completion counter
__device__ double d_acc[6];        // reset by last fgloss block
__device__ float4 d_cbox [BB * SP];   // x1,y1,x2,y2
__device__ float4 d_cmeta[BB * SP];   // area, obj, suml, -

// ---------------- block reduction helper ----------------
__device__ __forceinline__ float blockSum(float v, float* s) {
    int tid = threadIdx.x;
#pragma unroll
    for (int o = 16; o > 0; o >>= 1) v += __shfl_xor_sync(0xffffffffu, v, o);
    if ((tid & 31) == 0) s[tid >> 5] = v;
    __syncthreads();
    float r = 0.0f;
    if (tid < (blockDim.x >> 5)) r = s[tid];
#pragma unroll
    for (int o = 4; o > 0; o >>= 1) r += __shfl_xor_sync(0xffffffffu, r, o);
    __syncthreads();
    return r;   // valid in thread 0
}

// ---------------- kernel 1: analytic mask + fg-independent obj BCE ----------
__global__ void k_isin(const float* __restrict__ labels,
                       const float* __restrict__ outp) {
    __shared__ float sgx[GG], sgy[GG];
    __shared__ float s[8];
    int b = blockIdx.y;
    int tid = threadIdx.x;
    if (tid < GG) {
        sgx[tid] = labels[(b * GG + tid) * 5 + 1];
        sgy[tid] = labels[(b * GG + tid) * 5 + 2];
    }
    // zero the transposed in-region bits (61440 words) across the grid
    int gt = (blockIdx.y * gridDim.x + blockIdx.x) * blockDim.x + tid;
    if (gt < BB * GG * SPW) d_ginin[gt] = 0u;
    __syncthreads();
    int a = blockIdx.x * blockDim.x + tid;
    float vo = 0.0f;
    if (a < AA) {
        float sc; int n, rel;
        if (a < 6400)      { sc = 8.0f;  n = 80; rel = a;        }
        else if (a < 8000) { sc = 16.0f; n = 40; rel = a - 6400; }
        else               { sc = 32.0f; n = 20; rel = a - 8000; }
        float xc = ((float)(rel % n) + 0.5f) * sc;
        float yc = ((float)(rel / n) + 0.5f) * sc;
        float r  = 1.5f * sc;
        unsigned long long m = 0ull;
#pragma unroll 8
        for (int g = 0; g < GG; g++) {
            bool in = (xc > sgx[g] - r) && (xc < sgx[g] + r) &&
                      (yc > sgy[g] - r) && (yc < sgy[g] + r);
            if (in) m |= (1ull << g);
        }
        d_inin [b * AA + a] = m;
        d_match[b * AA + a] = 0ull;
        float x = outp[(size_t)(b * AA + a) * ROW + 4];
        vo = fmaxf(x, 0.0f) + __logf(1.0f + __expf(-fabsf(x)));
    }
    float r = blockSum(vo, s);
    if (tid == 0) atomicAdd(&d_acc[1], (double)r);
}

// ---------------- kernel 2: ordered compaction + transposed mask write -------
__global__ void __launch_bounds__(1024) k_scan() {
    __shared__ int wcnt[32];
    int b = blockIdx.x;
    int tid = threadIdx.x, wid = tid >> 5, lane = tid & 31;
    const int CH = 263;
    int base = wid * CH;
    int cnt = 0;
#pragma unroll
    for (int k = 0; k < 9; k++) {
        int loc = k * 32 + lane;
        int a = base + loc;
        bool p = (loc < CH) && (a < AA) && (d_inin[b * AA + a] != 0ull);
        cnt += __popc(__ballot_sync(0xffffffffu, p));
    }
    if (lane == 0) wcnt[wid] = cnt;
    __syncthreads();
    if (wid == 0) {
        int v = wcnt[lane];
#pragma unroll
        for (int o = 1; o < 32; o <<= 1) {
            int u = __shfl_up_sync(0xffffffffu, v, o);
            if (lane >= o) v += u;
        }
        wcnt[lane] = v;
    }
    __syncthreads();
    if (tid == 0) {
        int tot = wcnt[31];
        d_fgcnt[b] = tot < SP ? tot : SP;
    }
    int pos = wcnt[wid] - cnt;
#pragma unroll
    for (int k = 0; k < 9; k++) {
        int loc = k * 32 + lane;
        int a = base + loc;
        unsigned long long m =
            ((loc < CH) && (a < AA)) ? d_inin[b * AA + a] : 0ull;
        unsigned bal = __ballot_sync(0xffffffffu, m != 0ull);
        int my = __popc(bal & ((1u << lane) - 1u));
        if (m != 0ull && pos + my < SP) {
            int cp = pos + my;
            d_fgidx[b * SP + cp] = a;
            d_inv  [b * AA + a]  = cp;
            unsigned long long mm = m;
            while (mm) {
                int g = __ffsll((long long)mm) - 1;
                mm &= mm - 1;
                atomicOr(&d_ginin[(b * GG + g) * SPW + (cp >> 5)],
                         1u << (cp & 31));
            }
        }
        pos += __popc(bal);
    }
}

// ---------------- kernel 3: candidate prep + suml (16 lanes / candidate) -----
__global__ void __launch_bounds__(128) k_prep(const float* __restrict__ outp) {
    int b   = blockIdx.y;
    int cnt = d_fgcnt[b];
    if (blockIdx.x * 8 >= cnt) return;
    int tid  = threadIdx.x;
    int lane = tid & 31, warp = tid >> 5;
    int grp  = lane >> 4, sub = lane & 15;
    int i    = blockIdx.x * 8 + warp * 2 + grp;
    bool valid = (i < cnt);
    int ic = valid ? i : (cnt - 1);
    int a  = d_fgidx[b * SP + ic];
    const float* o = outp + (size_t)(b * AA + a) * ROW;
    float obj = o[4];
    float prod = 1.0f;
#pragma unroll
    for (int c = 0; c < 5; c++) {
        float x = o[5 + sub * 5 + c] * obj;
        prod *= (1.0f - x * rsqrtf(x));
    }
    float l = __logf(prod);
    l += __shfl_xor_sync(0xffffffffu, l, 1);
    l += __shfl_xor_sync(0xffffffffu, l, 2);
    l += __shfl_xor_sync(0xffffffffu, l, 4);
    l += __shfl_xor_sync(0xffffffffu, l, 8);
    if (sub == 0 && valid) {
        float bx = o[0], by = o[1], bw = o[2], bh = o[3];
        int idx = b * SP + i;
        d_cbox [idx] = make_float4(bx - bw * 0.5f, by - bh * 0.5f,
                                   bx + bw * 0.5f, by + bh * 0.5f);
        d_cmeta[idx] = make_float4(bw * bh, obj, l, 0.0f);
        d_cinin[idx] = d_inin[b * AA + a];
    }
}

// ---------------- kernel 4: fused pair iou + dynamic_k + top-k select -------
// Block per (b,g), 256 threads x 6 candidates.
// j-loop: iou + ballot-append of (nonzero iou) values and (in-region) keys.
// Warp 0 alone: top-10 sum over the ~10-30-entry nonzero list, then k-pass
// stable min-selection over the in-region cost list, batched atomics.
__global__ void __launch_bounds__(256) k_pairsel(const float* __restrict__ outp,
                                                 const float* __restrict__ labels) {
    __shared__ unsigned sioul[SP];               // nonzero iou values
    __shared__ unsigned long long slist[SL];     // in-region (costkey|idx)
    __shared__ unsigned long long swin[10];
    __shared__ int scnt, scnt2;
    int bg = blockIdx.x;
    int b  = bg / GG;
    int g  = bg - b * GG;
    int tid = threadIdx.x, lane = tid & 31, wid = tid >> 5;
    int N = d_fgcnt[b];
    if (tid == 0) { scnt = 0; scnt2 = 0; }

    const float* L = labels + (b * GG + g) * 5;   // uniform broadcast loads
    int   gc  = (int)L[0];
    float gxv = L[1], gyv = L[2], gwv = L[3], ghv = L[4];
    float qx1 = gxv - gwv * 0.5f, qx2 = gxv + gwv * 0.5f;
    float qy1 = gyv - ghv * 0.5f, qy2 = gyv + ghv * 0.5f;
    float qar = gwv * ghv;
    const unsigned* gin = d_ginin + (size_t)bg * SPW;
    __syncthreads();                              // scnt/scnt2 visible

#pragma unroll
    for (int j = 0; j < 6; j++) {
        int i = tid + j * 256;
        float iou = 0.0f;
        bool inreg = false;
        if (i < N) {
            float4 box = d_cbox[b * SP + i];
            float area = (box.z - box.x) * (box.w - box.y);
            float w = fminf(box.z, qx2) - fmaxf(box.x, qx1);
            float h = fminf(box.w, qy2) - fmaxf(box.y, qy1);
            float inter = fmaxf(w, 0.0f) * fmaxf(h, 0.0f);
            float den = area + qar - inter;
            float y = __uint_as_float(0x7EF311C3u - __float_as_uint(den));
            y = y * (2.0f - den * y);
            y = y * (2.0f - den * y);
            iou = inter * y;
            unsigned wrd = gin[wid + 8 * j];      // warp-uniform word
            inreg = (wrd >> lane) & 1u;
        }
        // append nonzero iou values (indices irrelevant for a sum)
        bool nz = (iou > 0.0f);
        unsigned mb = __ballot_sync(0xffffffffu, nz);
        if (mb) {
            int leader = __ffs(mb) - 1;
            int base = 0;
            if (lane == leader) base = atomicAdd(&scnt2, __popc(mb));
            base = __shfl_sync(0xffffffffu, base, leader);
            if (nz) sioul[base + __popc(mb & ((1u << lane) - 1u))] =
                        __float_as_uint(iou);
        }
        // append in-region (iou, i) for the cost pass
        mb = __ballot_sync(0xffffffffu, inreg);
        if (mb) {
            int leader = __ffs(mb) - 1;
            int base = 0;
            if (lane == leader) base = atomicAdd(&scnt, __popc(mb));
            base = __shfl_sync(0xffffffffu, base, leader);
            if (inreg) {
                int p = base + __popc(mb & ((1u << lane) - 1u));
                if (p < SL)
                    slist[p] = ((unsigned long long)__float_as_uint(iou) << 32)
                               | (unsigned)i;
            }
        }
    }
    __syncthreads();                              // lists complete

    // cost burst: parallel over the <=SL in-region entries
    int M = scnt; if (M > SL) M = SL;
    if (tid < M) {
        unsigned long long e = slist[tid];
        int i = (int)(unsigned)(e & 0xFFFFFFFFull);
        float iou = __uint_as_float((unsigned)(e >> 32));
        int idx = b * SP + i;
        float4 meta = d_cmeta[idx];
        int a = d_fgidx[idx];
        float xg = outp[(size_t)(b * AA + a) * ROW + 5 + gc] * meta.y;
        float pg = xg * rsqrtf(xg);
        float cost = -meta.z - (0.5f * __logf(xg) - __logf(1.0f - pg))
                     - 3.0f * __logf(iou + 1e-8f);
        unsigned cb = __float_as_uint(cost);
        cb = (cb & 0x80000000u) ? ~cb : (cb | 0x80000000u);
        slist[tid] = ((unsigned long long)cb << 32) | (unsigned)i;
    }
    __syncthreads();

    if (wid != 0) return;
    // warp0: top-10 sum over the nonzero-iou list (descending accumulation)
    int M2 = scnt2;
    float sum = 0.0f;
    for (int t = 0; t < 10; t++) {
        float lmax = 0.0f; int lidx = -1;
        for (int p = lane; p < M2; p += 32) {
            float v = __uint_as_float(sioul[p]);
            if (v > lmax) { lmax = v; lidx = p; }
        }
        float wmax = lmax;
#pragma unroll
        for (int o = 16; o > 0; o >>= 1)
            wmax = fmaxf(wmax, __shfl_xor_sync(0xffffffffu, wmax, o));
        if (wmax <= 0.0f) break;                  // no nonzero values left
        unsigned ball = __ballot_sync(0xffffffffu, lmax == wmax);
        if (lane == (__ffs(ball) - 1)) sioul[lidx] = 0u;  // pop one instance
        sum += wmax;
    }
    int k = (int)sum;
    if (k < 1)  k = 1;
    if (k > 10) k = 10;

    // phase B: k smallest (cost, idx) keys; collect winners, batch atomics
    unsigned long long kk0 = (lane      < M) ? slist[lane]      : ~0ull;
    unsigned long long kk1 = (lane + 32 < M) ? slist[lane + 32] : ~0ull;
    int nwin = 0;
    for (int t = 0; t < k; t++) {
        unsigned long long lbest = (kk0 < kk1) ? kk0 : kk1;
        unsigned long long wmin = lbest;
#pragma unroll
        for (int o = 16; o > 0; o >>= 1) {
            unsigned long long oth = __shfl_xor_sync(0xffffffffu, wmin, o);
            if (oth < wmin) wmin = oth;
        }
        if (wmin == ~0ull) break;
        unsigned ball = __ballot_sync(0xffffffffu, lbest == wmin);
        if (lane == (__ffs(ball) - 1)) {          // keys unique: remove
            if (kk0 == wmin) kk0 = ~0ull; else kk1 = ~0ull;
        }
        if (lane == 0) swin[t] = wmin;
        nwin++;
    }
    __syncwarp();
    if (lane < nwin) {                            // parallel atomics (distinct a)
        int i = (int)(unsigned)(swin[lane] & 0xFFFFFFFFull);
        int a = d_fgidx[b * SP + i];
        unsigned long long old = atomicOr(&d_match[b * AA + a], 1ull << g);
        if (old == 0ull) {                        // first match -> compact
            int pos = atomicAdd(&d_mcnt[b], 1);
            if (pos < MM) d_midx[b * MM + pos] = a;
        }
    }
}

// ---------------- kernel 5: matched-anchor losses + last-block finalize ------
__global__ void __launch_bounds__(128) k_fgloss(const float* __restrict__ outp,
                                                const float* __restrict__ orig,
                                                const float* __restrict__ labels,
                                                const float* __restrict__ xsA,
                                                const float* __restrict__ ysA,
                                                const float* __restrict__ stA,
                                                float* __restrict__ out,
                                                int nblocks) {
    __shared__ float s[8];
    int b = blockIdx.y;
    int j = blockIdx.x * 128 + threadIdx.x;
    float v_iou = 0.0f, v_cls = 0.0f, v_l1 = 0.0f, v_obj = 0.0f;
    int mc2 = d_mcnt[b]; if (mc2 > MM) mc2 = MM;
    if (j < mc2) {
        int a = d_midx[b * MM + j];
        unsigned long long m = d_match[b * AA + a];
        int i = d_inv[b * AA + a];
        int idx = b * SP + i;
        int mg;
        if (__popcll(m) > 1) {
            // best_gt = argmin cost over in-region g's (identical formulas to
            // k_pairsel; out-of-region +1e6 costs can never win)
            float4 box  = d_cbox [idx];
            float4 meta = d_cmeta[idx];
            unsigned long long mm = d_cinin[idx];
            const float* orow = outp + (size_t)(b * AA + a) * ROW;
            float best = FLT_MAX; mg = 0;
            while (mm) {
                int g = __ffsll((long long)mm) - 1;
                mm &= mm - 1;
                const float* L = labels + (b * GG + g) * 5;
                int   gc  = (int)L[0];
                float gxv = L[1], gyv = L[2], gwv = L[3], ghv = L[4];
                float qx1 = gxv - gwv * 0.5f, qx2 = gxv + gwv * 0.5f;
                float qy1 = gyv - ghv * 0.5f, qy2 = gyv + ghv * 0.5f;
                float qar = gwv * ghv;
                float w = fminf(box.z, qx2) - fmaxf(box.x, qx1);
                float h = fminf(box.w, qy2) - fmaxf(box.y, qy1);
                float inter = fmaxf(w, 0.0f) * fmaxf(h, 0.0f);
                float den = meta.x + qar - inter;
                float y = __uint_as_float(0x7EF311C3u - __float_as_uint(den));
                y = y * (2.0f - den * y);
                y = y * (2.0f - den * y);
                float iou = inter * y;
                float xg = orow[5 + gc] * meta.y;
                float pg = xg * rsqrtf(xg);
                float c = -meta.z - (0.5f * __logf(xg) - __logf(1.0f - pg))
                          - 3.0f * __logf(iou + 1e-8f);
                if (c < best) { best = c; mg = g; }
            }
        } else {
            mg = __ffsll((long long)m) - 1;
        }
        const float* L = labels + (b * GG + mg) * 5;
        int   mc = (int)L[0];
        float gxv = L[1], gyv = L[2], gwv = L[3], ghv = L[4];

        const float* o = outp + (size_t)(b * AA + a) * ROW;
        v_obj = -o[4];                       // fg-dependent obj BCE term
        float bx = o[0], by = o[1], bw = o[2], bh = o[3];
        float tlx = fmaxf(bx - bw * 0.5f, gxv - gwv * 0.5f);
        float tly = fmaxf(by - bh * 0.5f, gyv - ghv * 0.5f);
        float brx = fminf(bx + bw * 0.5f, gxv + gwv * 0.5f);
        float bry = fminf(by + bh * 0.5f, gyv + ghv * 0.5f);
        float inter = (tlx < brx && tly < bry) ? (brx - tlx) * (bry - tly) : 0.0f;
        float pred_iou = inter / (bw * bh + gwv * ghv - inter);
        float iou      = inter / (bw * bh + gwv * ghv - inter + 1e-16f);
        v_iou = 1.0f - iou * iou;

        float cl = 0.0f;
#pragma unroll 8
        for (int c = 0; c < CC; c++) {
            float xl = o[5 + c];
            float t  = (c == mc) ? pred_iou : 0.0f;
            cl += fmaxf(xl, 0.0f) - xl * t + log1pf(expf(-fabsf(xl)));
        }
        v_cls = cl;

        float st = stA[a];
        float t0 = gxv / st - xsA[a];
        float t1 = gyv / st - ysA[a];
        float t2 = logf(gwv / st + 1e-8f);
        float t3 = logf(ghv / st + 1e-8f);
        const float* op = orig + (size_t)(b * AA + a) * 4;
        v_l1 = fabsf(op[0] - t0) + fabsf(op[1] - t1) +
               fabsf(op[2] - t2) + fabsf(op[3] - t3);
    }
    float r;
    r = blockSum(v_iou, s); if (threadIdx.x == 0) atomicAdd(&d_acc[0], (double)r);
    r = blockSum(v_obj, s); if (threadIdx.x == 0) atomicAdd(&d_acc[1], (double)r);
    r = blockSum(v_cls, s); if (threadIdx.x == 0) atomicAdd(&d_acc[2], (double)r);
    r = blockSum(v_l1,  s); if (threadIdx.x == 0) atomicAdd(&d_acc[3], (double)r);

    // last-block finalize (deterministic: all sums are order-independent
    // double atomics; reset happens only after every block has finished)
    __shared__ int is_last;
    if (threadIdx.x == 0) {
        __threadfence();
        is_last = (atomicAdd(&d_done, 1) == nblocks - 1);
    }
    __syncthreads();
    if (is_last) {
        if (threadIdx.x == 0) {
            int tot = 0;
            for (int b2 = 0; b2 < BB; b2++) tot += d_mcnt[b2];
            double nfg = (double)tot;
            if (nfg < 1.0) nfg = 1.0;
            float liou = (float)(5.0 * d_acc[0] / nfg);
            float lobj = (float)(d_acc[1] / nfg);
            float lcls = (float)(d_acc[2] / nfg);
            float ll1  = (float)(d_acc[3] / nfg);
            out[0] = liou + lobj + lcls + ll1;
            out[1] = liou;
            out[2] = lobj;
            out[3] = lcls;
            out[4] = ll1;
            out[5] = (float)(nfg / (double)(BB * GG));
            d_done = 0;
        }
        __syncthreads();
        if (threadIdx.x < BB) d_mcnt[threadIdx.x] = 0;
        if (threadIdx.x < 6)  d_acc[threadIdx.x] = 0.0;
    }
}

// ---------------- launch ----------------
extern "C" void kernel_launch(void* const* d_in, const int* in_sizes, int n_in,
                              void* d_out, int out_size) {
    const float* outputs = (const float*)d_in[0];
    const float* origin  = (const float*)d_in[1];
    const float* labels  = (const float*)d_in[2];
    const float* xs      = (const float*)d_in[3];
    const float* ys      = (const float*)d_in[4];
    const float* st      = (const float*)d_in[5];

    k_isin<<<dim3((AA + 255) / 256, BB), 256>>>(labels, outputs);
    k_scan<<<BB, 1024>>>();
    k_prep<<<dim3(SP / 8, BB), 128>>>(outputs);
    k_pairsel<<<BB * GG, 256>>>(outputs, labels);
    k_fgloss<<<dim3(MM / 128, BB), 128>>>(outputs, origin, labels, xs, ys, st,
                                          (float*)d_out, (MM / 128) * BB);
}